// round 10
// baseline (speedup 1.0000x reference)
#include <cuda_runtime.h>

// ---------------------------------------------------------------------------
// FNet 2D FFT real part: x[8][4096][768] fp32 -> Re(FFT2 over (seq,hidden))
//
// Kernel A: seq FFT-4096 over Hermitian-packed hidden columns.
//   z_c[s] = x[s][2c] + i*x[s][2c+1], c = 0..383. TWO packed cols per
//   256-thread block (69.8 KB smem -> 3 blocks/SM). 3-pass register dft16.
//   Output Z complex, digit-reversed order jj, coalesced to
//   g_z[b][panel][jj][2] (16 B contiguous per jj).
// Kernel B: hidden FFT-768 per seq row; one warp per conjugate pair
//   (k, 4096-k). Loads Z rows rev(k), rev(4096-k); unpacks via Hermitian
//   symmetry; 3 x FFT-256 + radix-3 combine (real part only); writes TWO
//   full 768-float rows coalesced (second = first reversed).
// ---------------------------------------------------------------------------

__device__ __align__(16) float2 g_z[8ll * 192ll * 4096ll * 2ll];   // ~100 MB

__device__ __forceinline__ float2 cmul(float2 a, float2 b) {
    return make_float2(fmaf(a.x, b.x, -a.y * b.y), fmaf(a.x, b.y, a.y * b.x));
}

__device__ __forceinline__ int rev16_3(int k) {   // 3-digit base-16 reverse
    return ((k & 15) << 8) | (k & 0xF0) | (k >> 8);
}

// W16 twiddle constants
#define C16_1  0.9238795325112867f
#define S16_1  0.3826834323650898f
#define C16_2  0.7071067811865476f

__device__ __forceinline__ void radix4_ip(float2& a0, float2& a1, float2& a2, float2& a3) {
    float2 t0 = make_float2(a0.x + a2.x, a0.y + a2.y);
    float2 t1 = make_float2(a0.x - a2.x, a0.y - a2.y);
    float2 t2 = make_float2(a1.x + a3.x, a1.y + a3.y);
    float2 t3 = make_float2(a1.x - a3.x, a1.y - a3.y);
    a0 = make_float2(t0.x + t2.x, t0.y + t2.y);
    a1 = make_float2(t1.x + t3.y, t1.y - t3.x);   // t1 - i t3
    a2 = make_float2(t0.x - t2.x, t0.y - t2.y);
    a3 = make_float2(t1.x - t3.y, t1.y + t3.x);   // t1 + i t3
}

// Natural-order DFT-16 (DIT 4x4). Output Y_u lands at x[((u&3)<<2)|(u>>2)].
__device__ __forceinline__ void dft16(float2* x) {
    radix4_ip(x[0], x[4], x[8], x[12]);
    radix4_ip(x[1], x[5], x[9], x[13]);
    radix4_ip(x[2], x[6], x[10], x[14]);
    radix4_ip(x[3], x[7], x[11], x[15]);
    x[5]  = cmul(x[5],  make_float2( C16_1, -S16_1));   // W16^1
    x[6]  = cmul(x[6],  make_float2( C16_2, -C16_2));   // W16^2
    x[7]  = cmul(x[7],  make_float2( S16_1, -C16_1));   // W16^3
    x[9]  = cmul(x[9],  make_float2( C16_2, -C16_2));   // W16^2
    x[10] = make_float2(x[10].y, -x[10].x);             // W16^4 = -i
    x[11] = cmul(x[11], make_float2(-C16_2, -C16_2));   // W16^6
    x[13] = cmul(x[13], make_float2( S16_1, -C16_1));   // W16^3
    x[14] = cmul(x[14], make_float2(-C16_2, -C16_2));   // W16^6
    x[15] = cmul(x[15], make_float2(-C16_1,  S16_1));   // W16^9
    radix4_ip(x[0],  x[1],  x[2],  x[3]);
    radix4_ip(x[4],  x[5],  x[6],  x[7]);
    radix4_ip(x[8],  x[9],  x[10], x[11]);
    radix4_ip(x[12], x[13], x[14], x[15]);
}

// Store DFT-16 outputs with external twiddles w1^u via a shallow product tree.
__device__ __forceinline__ void store_tw16(float2* d, int base, int stride,
                                           float2 w1, const float2* xx) {
    d[base] = xx[0];
    float2 w2 = cmul(w1, w1);
    float2 w4 = cmul(w2, w2);
    float2 w8 = cmul(w4, w4);
    float2 w3 = cmul(w2, w1);
    d[base +  1 * stride] = cmul(xx[4],  w1);
    d[base +  2 * stride] = cmul(xx[8],  w2);
    d[base +  3 * stride] = cmul(xx[12], w3);
    d[base +  4 * stride] = cmul(xx[1],  w4);
    float2 w5 = cmul(w4, w1); d[base +  5 * stride] = cmul(xx[5],  w5);
    float2 w6 = cmul(w4, w2); d[base +  6 * stride] = cmul(xx[9],  w6);
    float2 w7 = cmul(w4, w3); d[base +  7 * stride] = cmul(xx[13], w7);
    d[base +  8 * stride] = cmul(xx[2],  w8);
    d[base +  9 * stride] = cmul(xx[6],  cmul(w8, w1));
    d[base + 10 * stride] = cmul(xx[10], cmul(w8, w2));
    d[base + 11 * stride] = cmul(xx[14], cmul(w8, w3));
    d[base + 12 * stride] = cmul(xx[3],  cmul(w8, w4));
    d[base + 13 * stride] = cmul(xx[7],  cmul(w8, w5));
    d[base + 14 * stride] = cmul(xx[11], cmul(w8, w6));
    d[base + 15 * stride] = cmul(xx[15], cmul(w8, w7));
}

// ---------------------------------------------------------------------------
// Kernel A: seq FFT-4096 over 2 packed columns, 256 threads, 3 blocks/SM
// ---------------------------------------------------------------------------
#define ASTRIDE 4360                         // >= 4350 (max padded idx)
#define A_SMEM_BYTES (2 * ASTRIDE * 8)       // 69760 B

__global__ __launch_bounds__(256, 3) void kernelA(const float* __restrict__ x) {
    extern __shared__ float2 sm[];
    float2* data = sm;                               // 2 * ASTRIDE float2
    const int tid = threadIdx.x;
    const int b   = blockIdx.y;
    const int bx  = blockIdx.x;                      // panel 0..191
    const int col = tid >> 7;                        // 0..1
    const int ct  = tid & 127;

    // load: row s contributes reals [4bx, 4bx+4) = 1 float4 -> 2 packed cols
    const float4* src = reinterpret_cast<const float4*>(x);
    const long long rowbase = (long long)b * 4096 * 192 + bx;
    #pragma unroll
    for (int it = 0; it < 16; it++) {
        int s = tid + it * 256;                      // 0..4095
        float4 v = src[rowbase + (long long)s * 192];
        int pp = s + (s >> 4);
        data[pp]           = make_float2(v.x, v.y);
        data[ASTRIDE + pp] = make_float2(v.z, v.w);
    }
    __syncthreads();

    float2* d = data + col * ASTRIDE;
    float2 xx[16];

    // ---- pass 1: gather stride 256, twiddle W_4096^{j*u} --------------------
    #pragma unroll 1
    for (int half = 0; half < 2; half++) {
        const int j = ct + half * 128;               // 0..255
        const int base = j + (j >> 4);
        #pragma unroll
        for (int v = 0; v < 16; v++) xx[v] = d[base + 272 * v];
        dft16(xx);
        float s, c;
        sincospif(-(float)j * (1.0f / 2048.0f), &s, &c);   // W_4096^j
        store_tw16(d, base, 272, make_float2(c, s), xx);
    }
    __syncthreads();

    // ---- pass 2: gather stride 16, twiddle W_256^{j*u} ----------------------
    #pragma unroll 1
    for (int half = 0; half < 2; half++) {
        const int cc = ct + half * 128;              // 0..255
        const int h = cc >> 4, j = cc & 15;
        const int base = 272 * h + j;
        #pragma unroll
        for (int v = 0; v < 16; v++) xx[v] = d[base + 17 * v];
        dft16(xx);
        float s, c;
        sincospif(-(float)j * (1.0f / 128.0f), &s, &c);    // W_256^j
        store_tw16(d, base, 17, make_float2(c, s), xx);
    }
    __syncthreads();

    // ---- pass 3: contiguous 16, no twiddle, store complex in place ----------
    #pragma unroll 1
    for (int half = 0; half < 2; half++) {
        const int m = ct + half * 128;               // 0..255
        const int base = 17 * m;
        #pragma unroll
        for (int v = 0; v < 16; v++) xx[v] = d[base + v];
        dft16(xx);
        #pragma unroll
        for (int u = 0; u < 16; u++) {
            const int p = ((u & 3) << 2) | (u >> 2);
            d[base + u] = xx[p];
        }
    }
    __syncthreads();

    // ---- readout: sequential jj, coalesced 16 B per jj ----------------------
    float2* gz = g_z + ((long long)(b * 192 + bx)) * 4096 * 2;
    #pragma unroll
    for (int it = 0; it < 16; it++) {
        const int jj = tid + it * 256;               // 0..4095 sequential
        const int pp = jj + (jj >> 4);
        float2 z0 = data[pp];
        float2 z1 = data[ASTRIDE + pp];
        *reinterpret_cast<float4*>(gz + (long long)jj * 2) =
            make_float4(z0.x, z0.y, z1.x, z1.y);
    }
}

// ---------------------------------------------------------------------------
// Kernel B: hidden FFT-768, one warp per conjugate row pair (k, 4096-k)
// ---------------------------------------------------------------------------
#define B_STRIDE 273                        // 256 + 15 pad + skew
#define B_SMEM_F2 (8 * 3 * B_STRIDE)        // 6552 float2 = 52416 B

__global__ __launch_bounds__(256) void kernelB(float* __restrict__ out) {
    extern __shared__ float2 sm[];
    const int tid  = threadIdx.x;
    const int ln   = tid & 31;
    const int w    = tid >> 5;
    const int b    = blockIdx.y;
    const int pk   = blockIdx.x * 8 + w;             // 0..2048 valid
    if (pk > 2048) return;

    float2* subs = sm + w * 3 * B_STRIDE;

    const int k1 = pk;
    const int k2 = (4096 - pk) & 4095;
    const int jj1 = rev16_3(k1);
    const int jj2 = rev16_3(k2);

    // load Z rows jj1, jj2 (384 complex each; lane handles 12 c's per row)
    float2 Z1[12], Z2[12];
    {
        const float2* gzb = g_z + (long long)b * 192 * 4096 * 2;
        #pragma unroll
        for (int t = 0; t < 12; t++) {
            const int c = ln + 32 * t;
            const int panel = c >> 1, pc = c & 1;
            const long long po = ((long long)panel * 4096) * 2 + pc;
            Z1[t] = gzb[po + (long long)jj1 * 2];
            Z2[t] = gzb[po + (long long)jj2 * 2];
        }
    }

    // unpack (Hermitian) and scatter into 3 decimated subsequences (l = 3m+sub)
    #pragma unroll
    for (int t = 0; t < 12; t++) {
        const int c = ln + 32 * t;
        // x-hat_{2c}   = (Z1 + conj Z2)/2
        // x-hat_{2c+1} = -i (Z1 - conj Z2)/2
        float2 ev = make_float2(0.5f * (Z1[t].x + Z2[t].x),
                                0.5f * (Z1[t].y - Z2[t].y));
        float2 od = make_float2(0.5f * (Z1[t].y + Z2[t].y),
                                0.5f * (Z2[t].x - Z1[t].x));
        int l0 = 2 * c, l1 = 2 * c + 1;
        int s0 = l0 % 3, m0 = l0 / 3;
        int s1 = l1 % 3, m1 = l1 / 3;
        subs[s0 * B_STRIDE + m0 + (m0 >> 4)] = ev;
        subs[s1 * B_STRIDE + m1 + (m1 >> 4)] = od;
    }
    __syncwarp();

    float2 xx[16];

    // pass A: 48 tasks (sub, j): gather stride 16, twiddle W_256^{j*u}
    #pragma unroll
    for (int r = 0; r < 2; r++) {
        const int t = ln + 32 * r;
        if (t < 48) {
            const int sub = t >> 4, j = t & 15;
            float2* d = subs + sub * B_STRIDE;
            #pragma unroll
            for (int v = 0; v < 16; v++) xx[v] = d[j + 17 * v];
            dft16(xx);
            float s, c;
            sincospif(-(float)j * (1.0f / 128.0f), &s, &c);   // W_256^j
            store_tw16(d, j, 17, make_float2(c, s), xx);
        }
    }
    __syncwarp();

    // pass B: 48 tasks (sub, h): contiguous 16, no twiddle
    #pragma unroll
    for (int r = 0; r < 2; r++) {
        const int t = ln + 32 * r;
        if (t < 48) {
            const int sub = t >> 4, h = t & 15;
            float2* d = subs + sub * B_STRIDE;
            #pragma unroll
            for (int v = 0; v < 16; v++) xx[v] = d[17 * h + v];
            dft16(xx);
            #pragma unroll
            for (int u = 0; u < 16; u++) {
                const int p = ((u & 3) << 2) | (u >> 2);
                d[17 * h + u] = xx[p];
            }
        }
    }
    __syncwarp();

    // combine (real part only): X[m] = F0 + W_768^m F1 + W_768^{2m} F2
    // write row k1 at m (coalesced) and row k2 at (768-m)%768 (coalesced).
    float* o1 = out + ((long long)b * 4096 + k1) * 768;
    float* o2 = out + ((long long)b * 4096 + k2) * 768;
    #pragma unroll
    for (int t = 0; t < 24; t++) {
        const int m = ln + 32 * t;                   // 0..767
        const int km = m & 255;
        const int p = ((km & 15) << 4) | (km >> 4);
        const int pp = p + (p >> 4);
        float2 F0 = subs[pp];
        float2 F1 = subs[B_STRIDE + pp];
        float2 F2 = subs[2 * B_STRIDE + pp];
        float s1, c1, s2, c2;
        sincospif(-(float)m * (1.0f / 384.0f), &s1, &c1);   // W_768^m
        sincospif(-(float)m * (1.0f / 192.0f), &s2, &c2);   // W_768^{2m}
        float re = F0.x + c1 * F1.x - s1 * F1.y + c2 * F2.x - s2 * F2.y;
        o1[m] = re;
        o2[m == 0 ? 0 : 768 - m] = re;
    }
}

// ---------------------------------------------------------------------------
extern "C" void kernel_launch(void* const* d_in, const int* in_sizes, int n_in,
                              void* d_out, int out_size) {
    const float* x = (const float*)d_in[0];
    float* out = (float*)d_out;
    (void)in_sizes; (void)n_in; (void)out_size;

    cudaFuncSetAttribute(kernelA,
                         cudaFuncAttributeMaxDynamicSharedMemorySize,
                         A_SMEM_BYTES);
    cudaFuncSetAttribute(kernelB,
                         cudaFuncAttributeMaxDynamicSharedMemorySize,
                         B_SMEM_F2 * (int)sizeof(float2));

    kernelA<<<dim3(192, 8), 256, A_SMEM_BYTES>>>(x);
    kernelB<<<dim3(257, 8), 256, B_SMEM_F2 * sizeof(float2)>>>(out);
}

// round 11
// speedup vs baseline: 1.1815x; 1.1815x over previous
#include <cuda_runtime.h>

// ---------------------------------------------------------------------------
// FNet 2D FFT real part: x[8][4096][768] fp32 -> Re(FFT2 over (seq,hidden))
//
// Kernel A: seq FFT-4096 over Hermitian-packed hidden columns.
//   z_c[s] = x[s][2c] + i*x[s][2c+1], c = 0..383. 4 packed cols per
//   512-thread block, 3-pass register dft16. Twiddle seeds from smem tables
//   (tw4096 / tw256) instead of per-thread sincospif. Output Z complex,
//   digit-reversed jj, coalesced 32 B per jj to g_z[b][panel][jj][4].
// Kernel B: hidden FFT-768 per seq row; one warp per conjugate pair
//   (k, 4096-k). W_768 twiddles from a 768-entry smem table. 3 x FFT-256 +
//   radix-3 combine (real part only); writes TWO full 768-float rows
//   coalesced (second = first reversed).
// ---------------------------------------------------------------------------

__device__ __align__(16) float2 g_z[8ll * 96ll * 4096ll * 4ll];   // ~100 MB

__device__ __forceinline__ float2 cmul(float2 a, float2 b) {
    return make_float2(fmaf(a.x, b.x, -a.y * b.y), fmaf(a.x, b.y, a.y * b.x));
}

__device__ __forceinline__ int rev16_3(int k) {   // 3-digit base-16 reverse
    return ((k & 15) << 8) | (k & 0xF0) | (k >> 8);
}

// W16 twiddle constants
#define C16_1  0.9238795325112867f
#define S16_1  0.3826834323650898f
#define C16_2  0.7071067811865476f

__device__ __forceinline__ void radix4_ip(float2& a0, float2& a1, float2& a2, float2& a3) {
    float2 t0 = make_float2(a0.x + a2.x, a0.y + a2.y);
    float2 t1 = make_float2(a0.x - a2.x, a0.y - a2.y);
    float2 t2 = make_float2(a1.x + a3.x, a1.y + a3.y);
    float2 t3 = make_float2(a1.x - a3.x, a1.y - a3.y);
    a0 = make_float2(t0.x + t2.x, t0.y + t2.y);
    a1 = make_float2(t1.x + t3.y, t1.y - t3.x);   // t1 - i t3
    a2 = make_float2(t0.x - t2.x, t0.y - t2.y);
    a3 = make_float2(t1.x - t3.y, t1.y + t3.x);   // t1 + i t3
}

// Natural-order DFT-16 (DIT 4x4). Output Y_u lands at x[((u&3)<<2)|(u>>2)].
__device__ __forceinline__ void dft16(float2* x) {
    radix4_ip(x[0], x[4], x[8], x[12]);
    radix4_ip(x[1], x[5], x[9], x[13]);
    radix4_ip(x[2], x[6], x[10], x[14]);
    radix4_ip(x[3], x[7], x[11], x[15]);
    x[5]  = cmul(x[5],  make_float2( C16_1, -S16_1));   // W16^1
    x[6]  = cmul(x[6],  make_float2( C16_2, -C16_2));   // W16^2
    x[7]  = cmul(x[7],  make_float2( S16_1, -C16_1));   // W16^3
    x[9]  = cmul(x[9],  make_float2( C16_2, -C16_2));   // W16^2
    x[10] = make_float2(x[10].y, -x[10].x);             // W16^4 = -i
    x[11] = cmul(x[11], make_float2(-C16_2, -C16_2));   // W16^6
    x[13] = cmul(x[13], make_float2( S16_1, -C16_1));   // W16^3
    x[14] = cmul(x[14], make_float2(-C16_2, -C16_2));   // W16^6
    x[15] = cmul(x[15], make_float2(-C16_1,  S16_1));   // W16^9
    radix4_ip(x[0],  x[1],  x[2],  x[3]);
    radix4_ip(x[4],  x[5],  x[6],  x[7]);
    radix4_ip(x[8],  x[9],  x[10], x[11]);
    radix4_ip(x[12], x[13], x[14], x[15]);
}

// Store DFT-16 outputs with external twiddles w1^u via a shallow product tree.
__device__ __forceinline__ void store_tw16(float2* d, int base, int stride,
                                           float2 w1, const float2* xx) {
    d[base] = xx[0];
    float2 w2 = cmul(w1, w1);
    float2 w4 = cmul(w2, w2);
    float2 w8 = cmul(w4, w4);
    float2 w3 = cmul(w2, w1);
    d[base +  1 * stride] = cmul(xx[4],  w1);
    d[base +  2 * stride] = cmul(xx[8],  w2);
    d[base +  3 * stride] = cmul(xx[12], w3);
    d[base +  4 * stride] = cmul(xx[1],  w4);
    float2 w5 = cmul(w4, w1); d[base +  5 * stride] = cmul(xx[5],  w5);
    float2 w6 = cmul(w4, w2); d[base +  6 * stride] = cmul(xx[9],  w6);
    float2 w7 = cmul(w4, w3); d[base +  7 * stride] = cmul(xx[13], w7);
    d[base +  8 * stride] = cmul(xx[2],  w8);
    d[base +  9 * stride] = cmul(xx[6],  cmul(w8, w1));
    d[base + 10 * stride] = cmul(xx[10], cmul(w8, w2));
    d[base + 11 * stride] = cmul(xx[14], cmul(w8, w3));
    d[base + 12 * stride] = cmul(xx[3],  cmul(w8, w4));
    d[base + 13 * stride] = cmul(xx[7],  cmul(w8, w5));
    d[base + 14 * stride] = cmul(xx[11], cmul(w8, w6));
    d[base + 15 * stride] = cmul(xx[15], cmul(w8, w7));
}

// ---------------------------------------------------------------------------
// Kernel A: seq FFT-4096 over 4 packed columns, 512 threads
// smem: tw4096[4096] | tw256[16] | data[4 * ASTRIDE]
// ---------------------------------------------------------------------------
#define ASTRIDE 4360                         // >= 4350 (max padded idx)
#define A_TW_F2 4112                         // 4096 + 16
#define A_SMEM_BYTES ((A_TW_F2 + 4 * ASTRIDE) * 8)   // 172416 B

__global__ __launch_bounds__(512) void kernelA(const float* __restrict__ x) {
    extern __shared__ float2 sm[];
    float2* tw4096 = sm;                             // W_4096^t, t<4096
    float2* tw256  = sm + 4096;                      // W_256^t, t<16
    float2* data   = sm + A_TW_F2;                   // 4 * ASTRIDE float2
    const int tid = threadIdx.x;
    const int b   = blockIdx.y;
    const int bx  = blockIdx.x;                      // panel 0..95
    const int col = tid >> 7;                        // 0..3
    const int ct  = tid & 127;

    // twiddle tables
    #pragma unroll
    for (int it = 0; it < 8; it++) {
        int i = tid + it * 512;
        float s, c;
        sincospif(-(float)i * (1.0f / 2048.0f), &s, &c);   // W_4096^i
        tw4096[i] = make_float2(c, s);
    }
    if (tid < 16) {
        float s, c;
        sincospif(-(float)tid * (1.0f / 128.0f), &s, &c);  // W_256^tid
        tw256[tid] = make_float2(c, s);
    }

    // load: row s contributes reals [8bx, 8bx+8) = 2 float4 -> 4 packed cols
    const float4* src = reinterpret_cast<const float4*>(x);
    const long long rowbase = (long long)b * 4096 * 192 + 2 * bx;
    #pragma unroll
    for (int it = 0; it < 16; it++) {
        int fid = tid + it * 512;                    // 0..8191
        int s = fid >> 1, half = fid & 1;
        float4 v = src[rowbase + (long long)s * 192 + half];
        int c = half * 2;
        int pp = s + (s >> 4);
        data[c * ASTRIDE + pp]       = make_float2(v.x, v.y);
        data[(c + 1) * ASTRIDE + pp] = make_float2(v.z, v.w);
    }
    __syncthreads();

    float2* d = data + col * ASTRIDE;
    float2 xx[16];

    // ---- pass 1: gather stride 256, twiddle W_4096^{j*u} --------------------
    #pragma unroll 1
    for (int half = 0; half < 2; half++) {
        const int j = ct + half * 128;               // 0..255
        const int base = j + (j >> 4);
        #pragma unroll
        for (int v = 0; v < 16; v++) xx[v] = d[base + 272 * v];
        dft16(xx);
        store_tw16(d, base, 272, tw4096[j], xx);
    }
    __syncthreads();

    // ---- pass 2: gather stride 16, twiddle W_256^{j*u} ----------------------
    #pragma unroll 1
    for (int half = 0; half < 2; half++) {
        const int cc = ct + half * 128;              // 0..255
        const int h = cc >> 4, j = cc & 15;
        const int base = 272 * h + j;
        #pragma unroll
        for (int v = 0; v < 16; v++) xx[v] = d[base + 17 * v];
        dft16(xx);
        store_tw16(d, base, 17, tw256[j], xx);
    }
    __syncthreads();

    // ---- pass 3: contiguous 16, no twiddle, store complex in place ----------
    #pragma unroll 1
    for (int half = 0; half < 2; half++) {
        const int m = ct + half * 128;               // 0..255
        const int base = 17 * m;
        #pragma unroll
        for (int v = 0; v < 16; v++) xx[v] = d[base + v];
        dft16(xx);
        #pragma unroll
        for (int u = 0; u < 16; u++) {
            const int p = ((u & 3) << 2) | (u >> 2);
            d[base + u] = xx[p];
        }
    }
    __syncthreads();

    // ---- readout: sequential jj, coalesced 32 B per jj ----------------------
    float2* gz = g_z + ((long long)(b * 96 + bx)) * 4096 * 4;
    #pragma unroll
    for (int it = 0; it < 8; it++) {
        const int jj = tid + it * 512;               // 0..4095 sequential
        const int pp = jj + (jj >> 4);
        float2 z0 = data[0 * ASTRIDE + pp];
        float2 z1 = data[1 * ASTRIDE + pp];
        float2 z2 = data[2 * ASTRIDE + pp];
        float2 z3 = data[3 * ASTRIDE + pp];
        float4* w = reinterpret_cast<float4*>(gz + (long long)jj * 4);
        w[0] = make_float4(z0.x, z0.y, z1.x, z1.y);
        w[1] = make_float4(z2.x, z2.y, z3.x, z3.y);
    }
}

// ---------------------------------------------------------------------------
// Kernel B: hidden FFT-768, one warp per conjugate row pair (k, 4096-k)
// smem: tw768[768] | 8 warps x 3 subs x B_STRIDE
// ---------------------------------------------------------------------------
#define B_STRIDE 273                        // 256 + 15 pad + skew
#define B_SMEM_F2 (768 + 8 * 3 * B_STRIDE)  // 7320 float2 = 58560 B

__global__ __launch_bounds__(256) void kernelB(float* __restrict__ out) {
    extern __shared__ float2 sm[];
    float2* tw = sm;                                 // W_768^t, t<768
    const int tid  = threadIdx.x;
    const int ln   = tid & 31;
    const int w    = tid >> 5;
    const int b    = blockIdx.y;
    const int pk   = blockIdx.x * 8 + w;             // 0..2048 valid

    // twiddle table (all threads participate BEFORE any early exit)
    #pragma unroll
    for (int it = 0; it < 3; it++) {
        int i = tid + it * 256;
        float s, c;
        sincospif(-(float)i * (1.0f / 384.0f), &s, &c);   // W_768^i
        tw[i] = make_float2(c, s);
    }
    __syncthreads();

    if (pk > 2048) return;

    float2* subs = sm + 768 + w * 3 * B_STRIDE;

    const int k1 = pk;
    const int k2 = (4096 - pk) & 4095;
    const int jj1 = rev16_3(k1);
    const int jj2 = rev16_3(k2);

    // load Z rows jj1, jj2 (384 complex each; lane handles 12 c's per row)
    float2 Z1[12], Z2[12];
    {
        const float2* gzb = g_z + (long long)b * 96 * 4096 * 4;
        #pragma unroll
        for (int t = 0; t < 12; t++) {
            const int c = ln + 32 * t;
            const int panel = c >> 2, pc = c & 3;
            const long long po = ((long long)panel * 4096) * 4 + pc;
            Z1[t] = gzb[po + (long long)jj1 * 4];
            Z2[t] = gzb[po + (long long)jj2 * 4];
        }
    }

    // unpack (Hermitian) and scatter into 3 decimated subsequences (l = 3m+sub)
    #pragma unroll
    for (int t = 0; t < 12; t++) {
        const int c = ln + 32 * t;
        // x-hat_{2c}   = (Z1 + conj Z2)/2
        // x-hat_{2c+1} = -i (Z1 - conj Z2)/2
        float2 ev = make_float2(0.5f * (Z1[t].x + Z2[t].x),
                                0.5f * (Z1[t].y - Z2[t].y));
        float2 od = make_float2(0.5f * (Z1[t].y + Z2[t].y),
                                0.5f * (Z2[t].x - Z1[t].x));
        int l0 = 2 * c, l1 = 2 * c + 1;
        int s0 = l0 % 3, m0 = l0 / 3;
        int s1 = l1 % 3, m1 = l1 / 3;
        subs[s0 * B_STRIDE + m0 + (m0 >> 4)] = ev;
        subs[s1 * B_STRIDE + m1 + (m1 >> 4)] = od;
    }
    __syncwarp();

    float2 xx[16];

    // pass A: 48 tasks (sub, j): gather stride 16, twiddle W_256^j = W_768^{3j}
    #pragma unroll
    for (int r = 0; r < 2; r++) {
        const int t = ln + 32 * r;
        if (t < 48) {
            const int sub = t >> 4, j = t & 15;
            float2* d = subs + sub * B_STRIDE;
            #pragma unroll
            for (int v = 0; v < 16; v++) xx[v] = d[j + 17 * v];
            dft16(xx);
            store_tw16(d, j, 17, tw[3 * j], xx);
        }
    }
    __syncwarp();

    // pass B: 48 tasks (sub, h): contiguous 16, no twiddle
    #pragma unroll
    for (int r = 0; r < 2; r++) {
        const int t = ln + 32 * r;
        if (t < 48) {
            const int sub = t >> 4, h = t & 15;
            float2* d = subs + sub * B_STRIDE;
            #pragma unroll
            for (int v = 0; v < 16; v++) xx[v] = d[17 * h + v];
            dft16(xx);
            #pragma unroll
            for (int u = 0; u < 16; u++) {
                const int p = ((u & 3) << 2) | (u >> 2);
                d[17 * h + u] = xx[p];
            }
        }
    }
    __syncwarp();

    // combine (real part only): X[m] = F0 + W_768^m F1 + W_768^{2m} F2
    // write row k1 at m (coalesced) and row k2 at (768-m)%768 (coalesced).
    float* o1 = out + ((long long)b * 4096 + k1) * 768;
    float* o2 = out + ((long long)b * 4096 + k2) * 768;
    #pragma unroll
    for (int t = 0; t < 24; t++) {
        const int m = ln + 32 * t;                   // 0..767
        const int km = m & 255;
        const int p = ((km & 15) << 4) | (km >> 4);
        const int pp = p + (p >> 4);
        float2 F0 = subs[pp];
        float2 F1 = subs[B_STRIDE + pp];
        float2 F2 = subs[2 * B_STRIDE + pp];
        int i2m = 2 * m; if (i2m >= 768) i2m -= 768;
        float2 w1 = tw[m];
        float2 w2 = tw[i2m];
        float re = F0.x + w1.x * F1.x - w1.y * F1.y + w2.x * F2.x - w2.y * F2.y;
        o1[m] = re;
        o2[m == 0 ? 0 : 768 - m] = re;
    }
}

// ---------------------------------------------------------------------------
extern "C" void kernel_launch(void* const* d_in, const int* in_sizes, int n_in,
                              void* d_out, int out_size) {
    const float* x = (const float*)d_in[0];
    float* out = (float*)d_out;
    (void)in_sizes; (void)n_in; (void)out_size;

    cudaFuncSetAttribute(kernelA,
                         cudaFuncAttributeMaxDynamicSharedMemorySize,
                         A_SMEM_BYTES);
    cudaFuncSetAttribute(kernelB,
                         cudaFuncAttributeMaxDynamicSharedMemorySize,
                         B_SMEM_F2 * (int)sizeof(float2));

    kernelA<<<dim3(96, 8), 512, A_SMEM_BYTES>>>(x);
    kernelB<<<dim3(257, 8), 256, B_SMEM_F2 * sizeof(float2)>>>(out);
}